// round 15
// baseline (speedup 1.0000x reference)
#include <cuda_runtime.h>
#include <cuda_fp16.h>
#include <cstdint>

#define NF   40
#define ED   128
#define AD   128
#define NP   780     // 40*39/2
#define NPP  784     // 98 n-tiles of 8 pairs
#define NTHR 384     // 12 warps = 6 pair-groups x 2 a-slots
#define NWRP 12
#define XSTH 136     // halves per x row in smem (272B = 17 x 16B, 16B-aligned rows)

__device__ __forceinline__ uint32_t h2pack(float lo, float hi) {
    __half2 h = __floats2half2_rn(lo, hi);   // .x = lo
    return *(uint32_t*)&h;
}
__device__ __forceinline__ uint32_t h2bits(__half2 h) { return *(uint32_t*)&h; }

// D(m16n8) += A(m16k16, f16, row) * B(k16n8, f16, col), fp32 accum
__device__ __forceinline__ void mma16(float* d, const uint32_t* a, uint32_t b0, uint32_t b1) {
    asm volatile(
        "mma.sync.aligned.m16n8k16.row.col.f32.f16.f16.f32 "
        "{%0,%1,%2,%3}, {%4,%5,%6,%7}, {%8,%9}, {%0,%1,%2,%3};"
        : "+f"(d[0]), "+f"(d[1]), "+f"(d[2]), "+f"(d[3])
        : "r"(a[0]), "r"(a[1]), "r"(a[2]), "r"(a[3]), "r"(b0), "r"(b1));
}

__global__ void __launch_bounds__(NTHR, 1)
afm_kernel(const float* __restrict__ x,    // [B, F, E]
           const float* __restrict__ ww,   // [A, E]
           const float* __restrict__ wb,   // [A]
           const float* __restrict__ hw,   // [1, A]
           const float* __restrict__ pw,   // [1, E]
           const float* __restrict__ pb,   // [1]
           float* __restrict__ out)        // [B]
{
    __shared__ __half  xsh[NF * XSTH];    // ~10.6 KB, fp16 x, padded rows
    __shared__ __half  pwh[ED];           // fp16 p_w
    __shared__ float2  swh[AD];           // (wb[a], hw[a])
    __shared__ float   scs2[2][NPP];      // per-aslot partial scores
    __shared__ float   scs[NPP];
    __shared__ float   dvs[NPP];          // d[p] = hp_p . p_w
    __shared__ uint8_t pis[NPP], pjs[NPP];
    __shared__ float   red[3 * NWRP];

    const int tid  = threadIdx.x;
    const int wid  = tid >> 5, lane = tid & 31;
    const int g     = wid >> 1;       // pair-group 0..5
    const int aslot = wid & 1;        // owns a-rows [aslot*64, +64)
    const int q = lane >> 2, c = lane & 3;
    const int b = blockIdx.x;

    // ---- Stage x -> fp16 smem (padded stride) ----
    const float* xg = x + (size_t)b * (NF * ED);
    for (int idx = tid; idx < NF * (ED / 2); idx += NTHR) {
        int row = idx >> 6, pos = idx & 63;          // pos in half2 units
        float2 v = *(const float2*)&xg[row * ED + 2 * pos];
        *(__half2*)&xsh[row * XSTH + 2 * pos] = __floats2half2_rn(v.x, v.y);
    }
    for (int e = tid; e < ED; e += NTHR) pwh[e] = __float2half_rn(pw[e]);
    for (int a = tid; a < AD; a += NTHR) swh[a] = make_float2(wb[a], hw[a]);

    // ---- Pair index tables (triu i<j, i-major) ----
    for (int p = tid; p < NPP; p += NTHR) {
        if (p < NP) {
            int i = 0, rem = p;
            while (rem >= NF - 1 - i) { rem -= NF - 1 - i; i++; }
            pis[p] = (uint8_t)i; pjs[p] = (uint8_t)(i + 1 + rem);
        } else { pis[p] = 0; pjs[p] = 1; }
    }

    // ---- W fragments: 64 a-rows (4 m-tiles), fp16-packed, e-permuted:
    //      step s=2u+t: k{2c,2c+1} <-> e = 32u+8c+4t+{0,1};  k{2c+8,2c+9} <-> e+{2,3}
    const int A0 = aslot * 64;
    uint32_t wA[4][8][4];
    #pragma unroll
    for (int mt = 0; mt < 4; mt++) {
        #pragma unroll
        for (int s = 0; s < 8; s++) {
            int u = s >> 1, t = s & 1;
            int e0 = 32 * u + 8 * c + 4 * t;
            int r0 = (A0 + mt * 16 + q) * ED + e0;
            int r1 = r0 + 8 * ED;
            float4 w0 = *(const float4*)&ww[r0];
            float4 w1 = *(const float4*)&ww[r1];
            wA[mt][s][0] = h2pack(w0.x, w0.y);   // row q,   k{2c,2c+1}
            wA[mt][s][1] = h2pack(w1.x, w1.y);   // row q+8
            wA[mt][s][2] = h2pack(w0.z, w0.w);   // row q,   k{2c+8,2c+9}
            wA[mt][s][3] = h2pack(w1.z, w1.w);   // row q+8
        }
    }

    __syncthreads();

    // ---- Main loop: 98 tiles over 6 groups (17,17,16,16,16,16) ----
    const int nt0 = g * 16 + min(g, 2);
    const int nt1 = nt0 + 16 + (g < 2 ? 1 : 0);

    for (int nt = nt0; nt < nt1; nt++) {
        const int p = nt * 8 + q;                 // this quad's pair (B col)
        const __half* xi = &xsh[(int)pis[p] * XSTH + 8 * c];
        const __half* xj = &xsh[(int)pjs[p] * XSTH + 8 * c];
        const bool do_d = (aslot == (nt & 1));    // round-robin d-duty

        // 4 independent accumulator chains (one per m-tile), depth 8 each
        float acc[4][4] = {};
        float dacc = 0.f;

        #pragma unroll
        for (int u = 0; u < 4; u++) {
            // one LDS.128 per operand: 8 halves = e [32u+8c, +8)
            uint4 vi = *(const uint4*)&xi[32 * u];
            uint4 vj = *(const uint4*)&xj[32 * u];
            __half2 p0 = __hmul2(*(__half2*)&vi.x, *(__half2*)&vj.x);
            __half2 p1 = __hmul2(*(__half2*)&vi.y, *(__half2*)&vj.y);
            __half2 p2 = __hmul2(*(__half2*)&vi.z, *(__half2*)&vj.z);
            __half2 p3 = __hmul2(*(__half2*)&vi.w, *(__half2*)&vj.w);
            uint32_t b0 = h2bits(p0), b1 = h2bits(p1);
            uint32_t b2 = h2bits(p2), b3 = h2bits(p3);
            #pragma unroll
            for (int mt = 0; mt < 4; mt++) {
                mma16(acc[mt], wA[mt][2 * u],     b0, b1);
                mma16(acc[mt], wA[mt][2 * u + 1], b2, b3);
            }
            if (do_d) {
                uint4 vp = *(const uint4*)&pwh[32 * u + 8 * c];   // 8 fp16 pw
                float2 f0 = __half22float2(p0), f1 = __half22float2(p1);
                float2 f2 = __half22float2(p2), f3 = __half22float2(p3);
                float2 w0 = __half22float2(*(__half2*)&vp.x);
                float2 w1 = __half22float2(*(__half2*)&vp.y);
                float2 w2 = __half22float2(*(__half2*)&vp.z);
                float2 w3 = __half22float2(*(__half2*)&vp.w);
                dacc = fmaf(f0.x, w0.x, fmaf(f0.y, w0.y, fmaf(f1.x, w1.x, fmaf(f1.y, w1.y, dacc))));
                dacc = fmaf(f2.x, w2.x, fmaf(f2.y, w2.y, fmaf(f3.x, w3.x, fmaf(f3.y, w3.y, dacc))));
            }
        }
        if (do_d) {
            dacc += __shfl_xor_sync(0xffffffffu, dacc, 1);
            dacc += __shfl_xor_sync(0xffffffffu, dacc, 2);
            if (c == 0 && p < NP) dvs[p] = dacc;
        }

        // Fused epilogue: partial score over this warp's 64 a of h*relu(.+wb)
        float s0 = 0.f, s1 = 0.f;
        #pragma unroll
        for (int mt = 0; mt < 4; mt++) {
            float2 wh0 = swh[A0 + mt * 16 + q];       // row q
            float2 wh1 = swh[A0 + mt * 16 + q + 8];   // row q+8
            s0 += fmaxf(acc[mt][0] + wh0.x, 0.f) * wh0.y
                + fmaxf(acc[mt][2] + wh1.x, 0.f) * wh1.y;
            s1 += fmaxf(acc[mt][1] + wh0.x, 0.f) * wh0.y
                + fmaxf(acc[mt][3] + wh1.x, 0.f) * wh1.y;
        }
        #pragma unroll
        for (int o = 4; o <= 16; o <<= 1) {
            s0 += __shfl_xor_sync(0xffffffffu, s0, o);
            s1 += __shfl_xor_sync(0xffffffffu, s1, o);
        }
        if (lane < 4) {
            scs2[aslot][nt * 8 + 2 * lane]     = s0;
            scs2[aslot][nt * 8 + 2 * lane + 1] = s1;
        }
    }
    __syncthreads();

    for (int p = tid; p < NP; p += NTHR)
        scs[p] = scs2[0][p] + scs2[1][p];
    __syncthreads();

    // ---- Softmax over pairs + weighted sum (h_b softmax-invariant, dropped) ----
    float lmax = -3.4e38f;
    for (int p = tid; p < NP; p += NTHR) lmax = fmaxf(lmax, scs[p]);
    #pragma unroll
    for (int o = 16; o; o >>= 1) lmax = fmaxf(lmax, __shfl_xor_sync(0xffffffffu, lmax, o));
    if (lane == 0) red[wid] = lmax;
    __syncthreads();
    float m = red[0];
    #pragma unroll
    for (int w = 1; w < NWRP; w++) m = fmaxf(m, red[w]);

    float se = 0.f, sd = 0.f;
    for (int p = tid; p < NP; p += NTHR) {
        float e = __expf(scs[p] - m);
        se += e;
        sd = fmaf(e, dvs[p], sd);
    }
    #pragma unroll
    for (int o = 16; o; o >>= 1) {
        se += __shfl_xor_sync(0xffffffffu, se, o);
        sd += __shfl_xor_sync(0xffffffffu, sd, o);
    }
    if (lane == 0) { red[NWRP + wid] = se; red[2 * NWRP + wid] = sd; }
    __syncthreads();
    if (tid == 0) {
        float S = 0.f, D = 0.f;
        #pragma unroll
        for (int w = 0; w < NWRP; w++) { S += red[NWRP + w]; D += red[2 * NWRP + w]; }
        out[b] = D / S + pb[0];
    }
}

extern "C" void kernel_launch(void* const* d_in, const int* in_sizes, int n_in,
                              void* d_out, int out_size) {
    const float* x  = (const float*)d_in[0];
    const float* ww = (const float*)d_in[1];
    const float* wb = (const float*)d_in[2];
    const float* hw = (const float*)d_in[3];
    // d_in[4] = attn_h_b: uniform shift on scores, softmax-invariant -> unused
    const float* pw = (const float*)d_in[5];
    const float* pb = (const float*)d_in[6];
    float* out = (float*)d_out;

    int B = in_sizes[0] / (NF * ED);
    afm_kernel<<<B, NTHR>>>(x, ww, wb, hw, pw, pb, out);
}

// round 16
// speedup vs baseline: 1.0139x; 1.0139x over previous
#include <cuda_runtime.h>
#include <cuda_fp16.h>
#include <cstdint>

#define NF   40
#define ED   128
#define AD   128
#define NP   780     // 40*39/2
#define NPP  784     // 98 n-tiles of 8 pairs
#define NTHR 640     // 20 warps = 5 pair-groups x 4 a-slots
#define NWRP 20
#define XSTH 136     // halves per x row in smem (272B = 17 x 16B, 16B-aligned rows)

__device__ __forceinline__ uint32_t h2pack(float lo, float hi) {
    __half2 h = __floats2half2_rn(lo, hi);   // .x = lo
    return *(uint32_t*)&h;
}
__device__ __forceinline__ uint32_t h2bits(__half2 h) { return *(uint32_t*)&h; }

// D(m16n8) += A(m16k16, f16, row) * B(k16n8, f16, col), fp32 accum
__device__ __forceinline__ void mma16(float* d, const uint32_t* a, uint32_t b0, uint32_t b1) {
    asm volatile(
        "mma.sync.aligned.m16n8k16.row.col.f32.f16.f16.f32 "
        "{%0,%1,%2,%3}, {%4,%5,%6,%7}, {%8,%9}, {%0,%1,%2,%3};"
        : "+f"(d[0]), "+f"(d[1]), "+f"(d[2]), "+f"(d[3])
        : "r"(a[0]), "r"(a[1]), "r"(a[2]), "r"(a[3]), "r"(b0), "r"(b1));
}

__global__ void __launch_bounds__(NTHR, 1)
afm_kernel(const float* __restrict__ x,    // [B, F, E]
           const float* __restrict__ ww,   // [A, E]
           const float* __restrict__ wb,   // [A]
           const float* __restrict__ hw,   // [1, A]
           const float* __restrict__ pw,   // [1, E]
           const float* __restrict__ pb,   // [1]
           float* __restrict__ out)        // [B]
{
    __shared__ __half  xsh[NF * XSTH];    // ~10.6 KB, fp16 x, padded rows
    __shared__ __half  pwh[ED];           // fp16 p_w
    __shared__ float2  swh[AD];           // (wb[a], hw[a])
    __shared__ float   scs4[4][NPP];      // per-aslot partial scores
    __shared__ float   scs[NPP];
    __shared__ float   dvs[NPP];          // d[p] = hp_p . p_w
    __shared__ uint8_t pis[NPP], pjs[NPP];
    __shared__ float   red[3 * NWRP];

    const int tid  = threadIdx.x;
    const int wid  = tid >> 5, lane = tid & 31;
    const int g     = wid >> 2;       // pair-group 0..4
    const int aslot = wid & 3;        // owns a-rows [aslot*32, +32)
    const int q = lane >> 2, c = lane & 3;
    const int b = blockIdx.x;

    // ---- Stage x -> fp16 smem (padded stride) ----
    const float* xg = x + (size_t)b * (NF * ED);
    for (int idx = tid; idx < NF * (ED / 2); idx += NTHR) {
        int row = idx >> 6, pos = idx & 63;          // pos in half2 units
        float2 v = *(const float2*)&xg[row * ED + 2 * pos];
        *(__half2*)&xsh[row * XSTH + 2 * pos] = __floats2half2_rn(v.x, v.y);
    }
    for (int e = tid; e < ED; e += NTHR) pwh[e] = __float2half_rn(pw[e]);
    for (int a = tid; a < AD; a += NTHR) swh[a] = make_float2(wb[a], hw[a]);

    // ---- Pair index tables (triu i<j, i-major) ----
    for (int p = tid; p < NPP; p += NTHR) {
        if (p < NP) {
            int i = 0, rem = p;
            while (rem >= NF - 1 - i) { rem -= NF - 1 - i; i++; }
            pis[p] = (uint8_t)i; pjs[p] = (uint8_t)(i + 1 + rem);
        } else { pis[p] = 0; pjs[p] = 1; }
    }

    // ---- W fragments (register-stationary, fp16-packed), e-permuted:
    //      step s=2u+t: k{2c,2c+1} <-> e = 32u+8c+4t+{0,1};  k{2c+8,2c+9} <-> e+{2,3}
    const int A0 = aslot * 32;
    uint32_t wA[2][8][4];
    #pragma unroll
    for (int mt = 0; mt < 2; mt++) {
        #pragma unroll
        for (int s = 0; s < 8; s++) {
            int u = s >> 1, t = s & 1;
            int e0 = 32 * u + 8 * c + 4 * t;
            int r0 = (A0 + mt * 16 + q) * ED + e0;
            int r1 = r0 + 8 * ED;
            float4 w0 = *(const float4*)&ww[r0];
            float4 w1 = *(const float4*)&ww[r1];
            wA[mt][s][0] = h2pack(w0.x, w0.y);   // row q,   k{2c,2c+1}
            wA[mt][s][1] = h2pack(w1.x, w1.y);   // row q+8
            wA[mt][s][2] = h2pack(w0.z, w0.w);   // row q,   k{2c+8,2c+9}
            wA[mt][s][3] = h2pack(w1.z, w1.w);   // row q+8
        }
    }

    __syncthreads();

    // ---- Main loop: 98 tiles split 20/20/20/19/19 across 5 groups ----
    const int nt0 = (g <= 3) ? g * 20 : 79;
    const int nt1 = nt0 + ((g < 3) ? 20 : 19);

    for (int nt = nt0; nt < nt1; nt++) {
        const int p = nt * 8 + q;                 // this quad's pair (B col)
        const __half* xi = &xsh[(int)pis[p] * XSTH + 8 * c];
        const __half* xj = &xsh[(int)pjs[p] * XSTH + 8 * c];
        const bool do_d = (aslot == (nt & 3));    // round-robin d-duty

        // 2 accumulator chains (one per m-tile), depth 8 each
        float acc0[4] = {0.f, 0.f, 0.f, 0.f};
        float acc1[4] = {0.f, 0.f, 0.f, 0.f};
        float dacc = 0.f;

        #pragma unroll
        for (int u = 0; u < 4; u++) {
            // one LDS.128 per operand: 8 halves = e [32u+8c, +8)
            uint4 vi = *(const uint4*)&xi[32 * u];
            uint4 vj = *(const uint4*)&xj[32 * u];
            __half2 p0 = __hmul2(*(__half2*)&vi.x, *(__half2*)&vj.x);
            __half2 p1 = __hmul2(*(__half2*)&vi.y, *(__half2*)&vj.y);
            __half2 p2 = __hmul2(*(__half2*)&vi.z, *(__half2*)&vj.z);
            __half2 p3 = __hmul2(*(__half2*)&vi.w, *(__half2*)&vj.w);
            uint32_t b0 = h2bits(p0), b1 = h2bits(p1);
            uint32_t b2 = h2bits(p2), b3 = h2bits(p3);
            mma16(acc0, wA[0][2 * u],     b0, b1);
            mma16(acc1, wA[1][2 * u],     b0, b1);
            mma16(acc0, wA[0][2 * u + 1], b2, b3);
            mma16(acc1, wA[1][2 * u + 1], b2, b3);
            if (do_d) {
                uint4 vp = *(const uint4*)&pwh[32 * u + 8 * c];   // 8 fp16 pw
                float2 f0 = __half22float2(p0), f1 = __half22float2(p1);
                float2 f2 = __half22float2(p2), f3 = __half22float2(p3);
                float2 w0 = __half22float2(*(__half2*)&vp.x);
                float2 w1 = __half22float2(*(__half2*)&vp.y);
                float2 w2 = __half22float2(*(__half2*)&vp.z);
                float2 w3 = __half22float2(*(__half2*)&vp.w);
                dacc = fmaf(f0.x, w0.x, fmaf(f0.y, w0.y, fmaf(f1.x, w1.x, fmaf(f1.y, w1.y, dacc))));
                dacc = fmaf(f2.x, w2.x, fmaf(f2.y, w2.y, fmaf(f3.x, w3.x, fmaf(f3.y, w3.y, dacc))));
            }
        }
        if (do_d) {
            dacc += __shfl_xor_sync(0xffffffffu, dacc, 1);
            dacc += __shfl_xor_sync(0xffffffffu, dacc, 2);
            if (c == 0 && p < NP) dvs[p] = dacc;
        }

        // Fused epilogue: sum over this warp's 32 a of h*relu(.+wb)
        float s0 = 0.f, s1 = 0.f;
        #pragma unroll
        for (int u = 0; u < 4; u++) {
            float2 wh = swh[A0 + u * 8 + q];
            float au0 = (u < 2) ? acc0[2 * u]     : acc1[2 * (u - 2)];
            float au1 = (u < 2) ? acc0[2 * u + 1] : acc1[2 * (u - 2) + 1];
            s0 += fmaxf(au0 + wh.x, 0.f) * wh.y;
            s1 += fmaxf(au1 + wh.x, 0.f) * wh.y;
        }
        #pragma unroll
        for (int o = 4; o <= 16; o <<= 1) {
            s0 += __shfl_xor_sync(0xffffffffu, s0, o);
            s1 += __shfl_xor_sync(0xffffffffu, s1, o);
        }
        if (lane < 4) {
            scs4[aslot][nt * 8 + 2 * lane]     = s0;
            scs4[aslot][nt * 8 + 2 * lane + 1] = s1;
        }
    }
    __syncthreads();

    for (int p = tid; p < NP; p += NTHR)
        scs[p] = scs4[0][p] + scs4[1][p] + scs4[2][p] + scs4[3][p];
    __syncthreads();

    // ---- Softmax over pairs + weighted sum (h_b softmax-invariant, dropped) ----
    float lmax = -3.4e38f;
    for (int p = tid; p < NP; p += NTHR) lmax = fmaxf(lmax, scs[p]);
    #pragma unroll
    for (int o = 16; o; o >>= 1) lmax = fmaxf(lmax, __shfl_xor_sync(0xffffffffu, lmax, o));
    if (lane == 0) red[wid] = lmax;
    __syncthreads();
    float m = red[0];
    #pragma unroll
    for (int w = 1; w < NWRP; w++) m = fmaxf(m, red[w]);

    float se = 0.f, sd = 0.f;
    for (int p = tid; p < NP; p += NTHR) {
        float e = __expf(scs[p] - m);
        se += e;
        sd = fmaf(e, dvs[p], sd);
    }
    #pragma unroll
    for (int o = 16; o; o >>= 1) {
        se += __shfl_xor_sync(0xffffffffu, se, o);
        sd += __shfl_xor_sync(0xffffffffu, sd, o);
    }
    if (lane == 0) { red[NWRP + wid] = se; red[2 * NWRP + wid] = sd; }
    __syncthreads();
    if (tid == 0) {
        float S = 0.f, D = 0.f;
        #pragma unroll
        for (int w = 0; w < NWRP; w++) { S += red[NWRP + w]; D += red[2 * NWRP + w]; }
        out[b] = D / S + pb[0];
    }
}

extern "C" void kernel_launch(void* const* d_in, const int* in_sizes, int n_in,
                              void* d_out, int out_size) {
    const float* x  = (const float*)d_in[0];
    const float* ww = (const float*)d_in[1];
    const float* wb = (const float*)d_in[2];
    const float* hw = (const float*)d_in[3];
    // d_in[4] = attn_h_b: uniform shift on scores, softmax-invariant -> unused
    const float* pw = (const float*)d_in[5];
    const float* pb = (const float*)d_in[6];
    float* out = (float*)d_out;

    int B = in_sizes[0] / (NF * ED);
    afm_kernel<<<B, NTHR>>>(x, ww, wb, hw, pw, pb, out);
}

// round 17
// speedup vs baseline: 1.1967x; 1.1803x over previous
#include <cuda_runtime.h>
#include <cuda_fp16.h>
#include <cstdint>

#define NF   40
#define ED   128
#define AD   128
#define NP   780     // 40*39/2
#define NPP  784     // 98 n-tiles of 8 pairs
#define NTHR 512     // 16 warps = 4 pair-groups x 4 a-slots
#define NWRP 16
#define XSTH 136     // halves per x row in smem (272B = 17 x 16B)

// ---- dynamic smem layout (bytes) ----
#define OFF_STAGE 0                       // 2 x NF*ED*4 = 40960 (fp32 x double buffer)
#define OFF_XSH   40960                   // NF*XSTH*2 = 10880
#define OFF_PWH   51840                   // 256
#define OFF_SWH   52096                   // 1024
#define OFF_SCS4  53120                   // 4*784*4 = 12544
#define OFF_SCS   65664                   // 3136
#define OFF_DVS   68800                   // 3136
#define OFF_PIS   71936                   // 784
#define OFF_PJS   72720                   // 784
#define OFF_RED   73504                   // 192
#define SMEM_SZ   73728

__device__ __forceinline__ uint32_t h2pack(float lo, float hi) {
    __half2 h = __floats2half2_rn(lo, hi);
    return *(uint32_t*)&h;
}
__device__ __forceinline__ uint32_t h2bits(__half2 h) { return *(uint32_t*)&h; }

__device__ __forceinline__ void mma16(float* d, const uint32_t* a, uint32_t b0, uint32_t b1) {
    asm volatile(
        "mma.sync.aligned.m16n8k16.row.col.f32.f16.f16.f32 "
        "{%0,%1,%2,%3}, {%4,%5,%6,%7}, {%8,%9}, {%0,%1,%2,%3};"
        : "+f"(d[0]), "+f"(d[1]), "+f"(d[2]), "+f"(d[3])
        : "r"(a[0]), "r"(a[1]), "r"(a[2]), "r"(a[3]), "r"(b0), "r"(b1));
}

__device__ __forceinline__ void cpasync16(uint32_t saddr, const void* g) {
    asm volatile("cp.async.cg.shared.global [%0], [%1], 16;" :: "r"(saddr), "l"(g));
}
__device__ __forceinline__ void cpasync_commit() { asm volatile("cp.async.commit_group;"); }
__device__ __forceinline__ void cpasync_wait_all() { asm volatile("cp.async.wait_group 0;" ::: "memory"); }

__global__ void __launch_bounds__(NTHR, 1)
afm_kernel(const float* __restrict__ x,    // [B, F, E]
           const float* __restrict__ ww,   // [A, E]
           const float* __restrict__ wb,   // [A]
           const float* __restrict__ hw,   // [1, A]
           const float* __restrict__ pw,   // [1, E]
           const float* __restrict__ pb,   // [1]
           float* __restrict__ out,        // [B]
           int B)
{
    extern __shared__ char smem[];
    float*   stage = (float*)(smem + OFF_STAGE);    // [2][NF*ED]
    __half*  xsh  = (__half*)(smem + OFF_XSH);
    __half*  pwh  = (__half*)(smem + OFF_PWH);
    float2*  swh  = (float2*)(smem + OFF_SWH);
    float*   scs4 = (float*)(smem + OFF_SCS4);      // [4][NPP]
    float*   scs  = (float*)(smem + OFF_SCS);
    float*   dvs  = (float*)(smem + OFF_DVS);
    uint8_t* pis  = (uint8_t*)(smem + OFF_PIS);
    uint8_t* pjs  = (uint8_t*)(smem + OFF_PJS);
    float*   red  = (float*)(smem + OFF_RED);

    const int tid  = threadIdx.x;
    const int wid  = tid >> 5, lane = tid & 31;
    const int g     = wid >> 2;       // pair-group 0..3
    const int aslot = wid & 3;        // a-rows [aslot*32, +32)
    const int q = lane >> 2, c = lane & 3;

    // ---- Prefetch first batch's x (fp32) via cp.async into stage[0] ----
    {
        const float* xg = x + (size_t)blockIdx.x * (NF * ED);
        uint32_t sbase = (uint32_t)__cvta_generic_to_shared(stage);
        for (int idx = tid; idx < NF * ED / 4; idx += NTHR)
            cpasync16(sbase + 16 * idx, xg + 4 * idx);
        cpasync_commit();
    }

    // ---- One-time prologue (weights, tables) ----
    for (int e = tid; e < ED; e += NTHR) pwh[e] = __float2half_rn(pw[e]);
    for (int a = tid; a < AD; a += NTHR) swh[a] = make_float2(wb[a], hw[a]);
    for (int p = tid; p < NPP; p += NTHR) {
        if (p < NP) {
            int i = 0, rem = p;
            while (rem >= NF - 1 - i) { rem -= NF - 1 - i; i++; }
            pis[p] = (uint8_t)i; pjs[p] = (uint8_t)(i + 1 + rem);
        } else { pis[p] = 0; pjs[p] = 1; }
    }

    // W fragments (register-stationary, fp16-packed), e-permuted:
    //   step s=2u+t: k{2c,2c+1} <-> e = 32u+8c+4t+{0,1};  k{2c+8,2c+9} <-> e+{2,3}
    const int A0 = aslot * 32;
    uint32_t wA[2][8][4];
    #pragma unroll
    for (int mt = 0; mt < 2; mt++) {
        #pragma unroll
        for (int s = 0; s < 8; s++) {
            int u = s >> 1, t = s & 1;
            int e0 = 32 * u + 8 * c + 4 * t;
            int r0 = (A0 + mt * 16 + q) * ED + e0;
            int r1 = r0 + 8 * ED;
            float4 w0 = *(const float4*)&ww[r0];
            float4 w1 = *(const float4*)&ww[r1];
            wA[mt][s][0] = h2pack(w0.x, w0.y);
            wA[mt][s][1] = h2pack(w1.x, w1.y);
            wA[mt][s][2] = h2pack(w0.z, w0.w);
            wA[mt][s][3] = h2pack(w1.z, w1.w);
        }
    }

    const int nt0 = (g < 2) ? g * 25 : 50 + (g - 2) * 24;
    const int nt1 = nt0 + ((g < 2) ? 25 : 24);
    const float pbv = __ldg(&pb[0]);

    // ---- Persistent batch loop ----
    int k = 0;
    for (int b = blockIdx.x; b < B; b += gridDim.x, k++) {
        float* cur = stage + (k & 1) * (NF * ED);

        cpasync_wait_all();
        __syncthreads();                     // stage[k] ready; prev batch fully done

        // convert staged fp32 x -> fp16 xsh
        for (int idx = tid; idx < NF * (ED / 2); idx += NTHR) {
            int row = idx >> 6, pos = idx & 63;
            float2 v = *(const float2*)&cur[row * ED + 2 * pos];
            *(__half2*)&xsh[row * XSTH + 2 * pos] = __floats2half2_rn(v.x, v.y);
        }
        __syncthreads();

        // prefetch next batch's x (overlaps compute below)
        int bn = b + gridDim.x;
        if (bn < B) {
            const float* xg = x + (size_t)bn * (NF * ED);
            float* nxt = stage + ((k + 1) & 1) * (NF * ED);
            uint32_t sbase = (uint32_t)__cvta_generic_to_shared(nxt);
            for (int idx = tid; idx < NF * ED / 4; idx += NTHR)
                cpasync16(sbase + 16 * idx, xg + 4 * idx);
        }
        cpasync_commit();

        // ---- Main loop: 98 tiles split 25/25/24/24 ----
        for (int nt = nt0; nt < nt1; nt++) {
            const int p = nt * 8 + q;
            const __half* xi = &xsh[(int)pis[p] * XSTH + 8 * c];
            const __half* xj = &xsh[(int)pjs[p] * XSTH + 8 * c];
            const bool do_d = (aslot == (nt & 3));

            float accA0[4] = {0.f, 0.f, 0.f, 0.f};
            float accB0[4] = {0.f, 0.f, 0.f, 0.f};
            float accA1[4] = {0.f, 0.f, 0.f, 0.f};
            float accB1[4] = {0.f, 0.f, 0.f, 0.f};
            float dacc = 0.f;

            #pragma unroll
            for (int u = 0; u < 4; u++) {
                uint4 vi = *(const uint4*)&xi[32 * u];
                uint4 vj = *(const uint4*)&xj[32 * u];
                __half2 p0 = __hmul2(*(__half2*)&vi.x, *(__half2*)&vj.x);
                __half2 p1 = __hmul2(*(__half2*)&vi.y, *(__half2*)&vj.y);
                __half2 p2 = __hmul2(*(__half2*)&vi.z, *(__half2*)&vj.z);
                __half2 p3 = __hmul2(*(__half2*)&vi.w, *(__half2*)&vj.w);
                mma16(accA0, wA[0][2 * u],     h2bits(p0), h2bits(p1));
                mma16(accA1, wA[1][2 * u],     h2bits(p0), h2bits(p1));
                mma16(accB0, wA[0][2 * u + 1], h2bits(p2), h2bits(p3));
                mma16(accB1, wA[1][2 * u + 1], h2bits(p2), h2bits(p3));
                if (do_d) {
                    uint4 vp = *(const uint4*)&pwh[32 * u + 8 * c];
                    float2 f0 = __half22float2(p0), f1 = __half22float2(p1);
                    float2 f2 = __half22float2(p2), f3 = __half22float2(p3);
                    float2 w0 = __half22float2(*(__half2*)&vp.x);
                    float2 w1 = __half22float2(*(__half2*)&vp.y);
                    float2 w2 = __half22float2(*(__half2*)&vp.z);
                    float2 w3 = __half22float2(*(__half2*)&vp.w);
                    dacc = fmaf(f0.x, w0.x, fmaf(f0.y, w0.y, fmaf(f1.x, w1.x, fmaf(f1.y, w1.y, dacc))));
                    dacc = fmaf(f2.x, w2.x, fmaf(f2.y, w2.y, fmaf(f3.x, w3.x, fmaf(f3.y, w3.y, dacc))));
                }
            }
            if (do_d) {
                dacc += __shfl_xor_sync(0xffffffffu, dacc, 1);
                dacc += __shfl_xor_sync(0xffffffffu, dacc, 2);
                if (c == 0 && p < NP) dvs[p] = dacc;
            }

            float s0 = 0.f, s1 = 0.f;
            #pragma unroll
            for (int u = 0; u < 4; u++) {
                float2 wh = swh[A0 + u * 8 + q];
                float au0 = (u < 2) ? (accA0[2 * u] + accB0[2 * u])
                                    : (accA1[2 * (u - 2)] + accB1[2 * (u - 2)]);
                float au1 = (u < 2) ? (accA0[2 * u + 1] + accB0[2 * u + 1])
                                    : (accA1[2 * (u - 2) + 1] + accB1[2 * (u - 2) + 1]);
                s0 += fmaxf(au0 + wh.x, 0.f) * wh.y;
                s1 += fmaxf(au1 + wh.x, 0.f) * wh.y;
            }
            #pragma unroll
            for (int o = 4; o <= 16; o <<= 1) {
                s0 += __shfl_xor_sync(0xffffffffu, s0, o);
                s1 += __shfl_xor_sync(0xffffffffu, s1, o);
            }
            if (lane < 4) {
                scs4[aslot * NPP + nt * 8 + 2 * lane]     = s0;
                scs4[aslot * NPP + nt * 8 + 2 * lane + 1] = s1;
            }
        }
        __syncthreads();

        for (int p = tid; p < NP; p += NTHR)
            scs[p] = scs4[p] + scs4[NPP + p] + scs4[2 * NPP + p] + scs4[3 * NPP + p];
        __syncthreads();

        // ---- Softmax over pairs + weighted sum (h_b softmax-invariant, dropped) ----
        float lmax = -3.4e38f;
        for (int p = tid; p < NP; p += NTHR) lmax = fmaxf(lmax, scs[p]);
        #pragma unroll
        for (int o = 16; o; o >>= 1) lmax = fmaxf(lmax, __shfl_xor_sync(0xffffffffu, lmax, o));
        if (lane == 0) red[wid] = lmax;
        __syncthreads();
        float m = red[0];
        #pragma unroll
        for (int w = 1; w < NWRP; w++) m = fmaxf(m, red[w]);

        float se = 0.f, sd = 0.f;
        for (int p = tid; p < NP; p += NTHR) {
            float e = __expf(scs[p] - m);
            se += e;
            sd = fmaf(e, dvs[p], sd);
        }
        #pragma unroll
        for (int o = 16; o; o >>= 1) {
            se += __shfl_xor_sync(0xffffffffu, se, o);
            sd += __shfl_xor_sync(0xffffffffu, sd, o);
        }
        if (lane == 0) { red[NWRP + wid] = se; red[2 * NWRP + wid] = sd; }
        __syncthreads();
        if (tid == 0) {
            float S = 0.f, D = 0.f;
            #pragma unroll
            for (int w = 0; w < NWRP; w++) { S += red[NWRP + w]; D += red[2 * NWRP + w]; }
            out[b] = D / S + pbv;
        }
    }
}

extern "C" void kernel_launch(void* const* d_in, const int* in_sizes, int n_in,
                              void* d_out, int out_size) {
    const float* x  = (const float*)d_in[0];
    const float* ww = (const float*)d_in[1];
    const float* wb = (const float*)d_in[2];
    const float* hw = (const float*)d_in[3];
    // d_in[4] = attn_h_b: uniform shift on scores, softmax-invariant -> unused
    const float* pw = (const float*)d_in[5];
    const float* pb = (const float*)d_in[6];
    float* out = (float*)d_out;

    int B = in_sizes[0] / (NF * ED);

    int dev = 0, nsm = 148;
    cudaGetDevice(&dev);
    cudaDeviceGetAttribute(&nsm, cudaDevAttrMultiProcessorCount, dev);
    int grid = (B < nsm) ? B : nsm;

    cudaFuncSetAttribute(afm_kernel, cudaFuncAttributeMaxDynamicSharedMemorySize, SMEM_SZ);
    afm_kernel<<<grid, NTHR, SMEM_SZ>>>(x, ww, wb, hw, pw, pb, out, B);
}